// round 12
// baseline (speedup 1.0000x reference)
#include <cuda_runtime.h>
#include <math.h>
#include <float.h>

#define MROWS   4096
#define NCOLS   16384
#define KHARD   163          // int(0.01 * (16384-1))
#define DELTA_W 5.0f
#define THR0    2.0f
#define NT      128
#define NWARP   (NT / 32)
#define SLOTS   16           // per-thread scratch slots
#define NB      256          // linear value bins over [THR0, THR0+4)
#define GCAP    64
#define FULLM   0xFFFFFFFFu

__device__ float         g_scratch[(size_t)MROWS * SLOTS * NT];  // 32 MB
__device__ unsigned char g_tcnt[MROWS * NT];                     // 512 KB
__device__ float         g_partials[MROWS];
__device__ unsigned      g_done = 0;

__device__ __forceinline__ unsigned fkey(float x) {
    unsigned b = __float_as_uint(x);
    return (b & 0x80000000u) ? ~b : (b | 0x80000000u);
}
__device__ __forceinline__ float unfkey(unsigned k) {
    return (k & 0x80000000u) ? __uint_as_float(k ^ 0x80000000u) : __uint_as_float(~k);
}
__device__ __forceinline__ float softplus(float x) {
    return fmaxf(x, 0.0f) + log1pf(__expf(-fabsf(x)));
}
__device__ __forceinline__ int binof(float x) {          // x > THR0
    int b = (int)((x - THR0) * 64.0f);                   // NB/4 per unit
    return b > NB - 1 ? NB - 1 : b;
}

// ---------------- kernel 1: pure streaming sweep ----------------
extern "C" __global__ void __launch_bounds__(NT)
mmcl_sweep(const float* __restrict__ in)
{
    const int tid = threadIdx.x;
    const int row = blockIdx.x;
    const float4* __restrict__ p = (const float4*)(in + (size_t)row * NCOLS);
    float* __restrict__ slots = g_scratch + (size_t)row * (SLOTS * NT);

    unsigned mycnt = 0;
    #pragma unroll 8
    for (int it = 0; it < NCOLS / 4 / NT; ++it) {        // 32 iterations
        float4 f = __ldcs(&p[it * NT + tid]);
        if (f.x > THR0) { if (mycnt < SLOTS) slots[mycnt * NT + tid] = f.x; ++mycnt; }
        if (f.y > THR0) { if (mycnt < SLOTS) slots[mycnt * NT + tid] = f.y; ++mycnt; }
        if (f.z > THR0) { if (mycnt < SLOTS) slots[mycnt * NT + tid] = f.z; ++mycnt; }
        if (f.w > THR0) { if (mycnt < SLOTS) slots[mycnt * NT + tid] = f.w; ++mycnt; }
    }
    g_tcnt[row * NT + tid] = (unsigned char)mycnt;       // max 128, fits
}

// Boundary-bin search for the r-th largest over hist[0..B).
// s_out = {bin, count strictly above bin, bin count}. 2 barriers.
__device__ __forceinline__ void select_bin(const unsigned* __restrict__ hist, int B,
                                           unsigned r, unsigned* s_warpS,
                                           unsigned* s_out)
{
    const int tid = threadIdx.x, lane = tid & 31, wid = tid >> 5;
    const int c = (B + NT - 1) / NT;
    unsigned total = 0;
    const int base = tid * c;
    for (int j = 0; j < c; ++j)
        if (base + j < B) total += hist[base + j];
    unsigned incl = total;
    #pragma unroll
    for (int off = 1; off < 32; off <<= 1) {
        unsigned v = __shfl_down_sync(FULLM, incl, off);
        if (lane + off < 32) incl += v;
    }
    if (lane == 0) s_warpS[wid] = incl;
    __syncthreads();
    unsigned hi = 0;
    #pragma unroll
    for (int w = 0; w < NWARP; ++w) if (w > wid) hi += s_warpS[w];
    unsigned S = incl + hi;
    unsigned above_chunk = S - total;
    if (above_chunk < r && S >= r) {
        unsigned run = above_chunk;
        for (int j = c - 1; j >= 0; --j) {
            if (base + j >= B) continue;
            unsigned cnt = hist[base + j];
            if (run + cnt >= r) { s_out[0] = base + j; s_out[1] = run; s_out[2] = cnt; break; }
            run += cnt;
        }
    }
    __syncthreads();
}

// ---------------- kernel 2: per-row select + loss ----------------
extern "C" __global__ void __launch_bounds__(NT)
mmcl_select(const float* __restrict__ in, const int* __restrict__ tg,
            float* __restrict__ out)
{
    __shared__ unsigned hist[NB];
    __shared__ unsigned s_gn, s_flag;
    __shared__ unsigned s_warpS[NWARP];
    __shared__ unsigned s_out[3];
    __shared__ float    s_red[NWARP];
    __shared__ float    s_gath[GCAP];
    __shared__ float    s_bsum;

    const int tid  = threadIdx.x;
    const int lane = tid & 31;
    const int wid  = tid >> 5;
    const int row  = blockIdx.x;

    const float* __restrict__ rowp  = in + (size_t)row * NCOLS;
    const float* __restrict__ slots = g_scratch + (size_t)row * (SLOTS * NT);
    const int tgt = tg[row];

    for (int i = tid; i < NB / 4; i += NT)
        ((uint4*)hist)[i] = make_uint4(0, 0, 0, 0);
    if (tid == 0) s_gn = 0;

    const unsigned tc    = g_tcnt[row * NT + tid];
    const unsigned mycnt = tc < SLOTS ? tc : SLOTS;
    const float    pos   = rowp[tgt];

    // load own candidates into registers (coalesced across threads per slot)
    float loc[SLOTS];
    #pragma unroll
    for (int i = 0; i < SLOTS; ++i)
        loc[i] = (i < (int)mycnt) ? slots[i * NT + tid] : 0.0f;

    const unsigned wsum = __reduce_add_sync(FULLM, tc);
    const unsigned wovf = __ballot_sync(FULLM, tc > SLOTS);
    if (lane == 0) s_warpS[wid] = (wsum << 1) | (wovf ? 1u : 0u);
    __syncthreads();
    unsigned nc = 0, ovf = 0;
    #pragma unroll
    for (int w = 0; w < NWARP; ++w) { nc += s_warpS[w] >> 1; ovf |= s_warpS[w] & 1u; }

    const unsigned pos_in = (pos > THR0) ? 1u : 0u;
    bool gmode = (nc < KHARD + pos_in) || ovf;

    float sum = 0.0f;
    bool use_key = false;
    unsigned tkey = 0, rmul = 0;
    int bbin = NB;

    if (!gmode) {
        #pragma unroll
        for (int i = 0; i < SLOTS; ++i)
            if (i < (int)mycnt) atomicAdd(&hist[binof(loc[i])], 1u);
        if (tid == 0 && pos_in) atomicSub(&hist[binof(pos)], 1u);
        __syncthreads();

        select_bin(hist, NB, KHARD, s_warpS, s_out);
        bbin = (int)s_out[0];
        const unsigned rp = KHARD - s_out[1];   // rank within boundary bin

        // fused pass over OWN candidates: strict sum + boundary gather
        #pragma unroll
        for (int i = 0; i < SLOTS; ++i) {
            if (i < (int)mycnt) {
                float x = loc[i];
                int b = binof(x);
                if (b > bbin) sum += softplus(x);
                else if (b == bbin) {
                    unsigned g = atomicAdd(&s_gn, 1u);
                    if (g < GCAP) s_gath[g] = x;
                }
            }
        }
        __syncthreads();

        if (s_gn > GCAP) { gmode = true; sum = 0.0f; }
        else if (tid == 0) {
            int n = (int)s_gn;
            if (pos_in && binof(pos) == bbin) {  // drop one positive instance
                for (int j = 0; j < n; ++j)
                    if (s_gath[j] == pos) { s_gath[j] = s_gath[n - 1]; --n; break; }
            }
            float bs = 0.0f;                     // top-rp of the boundary bin
            for (int a = 0; a < (int)rp; ++a) {
                int mi = a; float mv = s_gath[a];
                for (int b2 = a + 1; b2 < n; ++b2)
                    if (s_gath[b2] > mv) { mv = s_gath[b2]; mi = b2; }
                s_gath[mi] = s_gath[a]; s_gath[a] = mv;
                bs += softplus(mv);
            }
            s_bsum = bs;
        }
    }

    if (gmode) {
        // exact 4x8-bit fkey radix select from the original row; never fires for N(0,1)
        use_key = true;
        unsigned prefix = 0, r = KHARD;
        for (int lev = 0; lev < 4; ++lev) {
            const int shift = 24 - 8 * lev;
            for (int i = tid; i < NB; i += NT) hist[i] = 0;
            __syncthreads();
            for (int j = tid; j < NCOLS; j += NT) {
                if (j == tgt) continue;
                unsigned u = fkey(rowp[j]);
                bool match = (lev == 0) || (((u ^ prefix) >> (shift + 8)) == 0u);
                if (match) atomicAdd(&hist[(u >> shift) & 255u], 1u);
            }
            __syncthreads();
            select_bin(hist, 256, r, s_warpS, s_out);
            prefix |= s_out[0] << shift;
            r -= s_out[1];
            __syncthreads();
        }
        tkey = prefix; rmul = r;
        for (int j = tid; j < NCOLS; j += NT) {
            if (j == tgt) continue;
            float x = rowp[j];
            if (fkey(x) > tkey) sum += softplus(x);
        }
    }

    // ---- block reduce strict sum, write row partial ----
    #pragma unroll
    for (int o = 16; o; o >>= 1) sum += __shfl_down_sync(FULLM, sum, o);
    if (lane == 0) s_red[wid] = sum;
    __syncthreads();

    if (tid == 0) {
        float tot = 0.0f;
        #pragma unroll
        for (int w = 0; w < NWARP; ++w) tot += s_red[w];
        if (!use_key) {
            if (pos_in && binof(pos) > bbin) tot -= softplus(pos);  // pos polluted strict sum
            tot += s_bsum;
        } else {
            tot += (float)rmul * softplus(unfkey(tkey));
        }
        g_partials[row] = DELTA_W * softplus(-pos) + tot / (float)KHARD;
        __threadfence();
        unsigned old = atomicAdd(&g_done, 1u);
        s_flag = (old == MROWS - 1) ? 1u : 0u;
    }
    __syncthreads();

    if (s_flag) {
        __threadfence();
        float s = 0.0f;
        for (int i = tid; i < MROWS; i += NT) s += __ldcg(&g_partials[i]);
        #pragma unroll
        for (int o = 16; o; o >>= 1) s += __shfl_down_sync(FULLM, s, o);
        if (lane == 0) s_red[wid] = s;
        __syncthreads();
        if (tid == 0) {
            float tot = 0.0f;
            #pragma unroll
            for (int w = 0; w < NWARP; ++w) tot += s_red[w];
            out[0] = tot / (float)MROWS;
            g_done = 0;                               // reset for next graph replay
        }
    }
}

extern "C" void kernel_launch(void* const* d_in, const int* in_sizes, int n_in,
                              void* d_out, int out_size)
{
    const float* in  = (const float*)d_in[0];
    const int*   tg  = (const int*)d_in[1];
    float*       out = (float*)d_out;
    mmcl_sweep<<<MROWS, NT>>>(in);
    mmcl_select<<<MROWS, NT>>>(in, tg, out);
}

// round 13
// speedup vs baseline: 1.1214x; 1.1214x over previous
#include <cuda_runtime.h>
#include <math.h>
#include <float.h>

#define MROWS   4096
#define NCOLS   16384
#define KHARD   163          // int(0.01 * (16384-1))
#define DELTA_W 5.0f
#define THR0    2.0f
#define NT      128
#define NWARP   (NT / 32)
#define SLOTS   16           // per-thread private candidate slots
#define NB      256          // linear value bins over [THR0, THR0+4)
#define GCAP    64
#define GRIDSZ  2048         // 2 rows per CTA, single wave at 14 CTAs/SM
#define SENT    0xFFFFFFFFu
#define FULLM   0xFFFFFFFFu

__device__ float    g_partials[MROWS];
__device__ unsigned g_done = 0;

__device__ __forceinline__ unsigned fkey(float x) {
    unsigned b = __float_as_uint(x);
    return (b & 0x80000000u) ? ~b : (b | 0x80000000u);
}
__device__ __forceinline__ float unfkey(unsigned k) {
    return (k & 0x80000000u) ? __uint_as_float(k ^ 0x80000000u) : __uint_as_float(~k);
}
__device__ __forceinline__ float softplus(float x) {
    return fmaxf(x, 0.0f) + log1pf(__expf(-fabsf(x)));
}
__device__ __forceinline__ int binof(float x) {          // x > THR0
    int b = (int)((x - THR0) * 64.0f);                   // NB/4 per unit
    return b > NB - 1 ? NB - 1 : b;
}
__device__ __forceinline__ void prefetch_l2(const float* p) {
    asm volatile("prefetch.global.L2 [%0];" :: "l"(p));
}

// Warp-0-only boundary-bin search for the r-th largest over hist[0..256).
// Leaves s_out[0] untouched (sentinel) when total < r. Caller owns barriers.
__device__ __forceinline__ void select256_w0(const unsigned* __restrict__ hist,
                                             unsigned r, unsigned* s_out)
{
    const int tid = threadIdx.x, lane = tid & 31;
    if (tid < 32) {
        const int base = lane * 8;
        unsigned total = 0;
        #pragma unroll
        for (int j = 0; j < 8; ++j) total += hist[base + j];
        unsigned incl = total;                    // inclusive suffix over lanes
        #pragma unroll
        for (int off = 1; off < 32; off <<= 1) {
            unsigned v = __shfl_down_sync(FULLM, incl, off);
            if (lane + off < 32) incl += v;
        }
        unsigned above = incl - total;            // count in strictly-higher lanes
        if (above < r && incl >= r) {             // boundary in my 8 bins
            unsigned run = above;
            #pragma unroll
            for (int j = 7; j >= 0; --j) {
                unsigned cnt = hist[base + j];
                if (run + cnt >= r) { s_out[0] = base + j; s_out[1] = run; s_out[2] = cnt; break; }
                run += cnt;
            }
        }
    }
}

extern "C" __global__ void __launch_bounds__(NT, 14)
mmcl_kernel(const float* __restrict__ in, const int* __restrict__ tg,
            float* __restrict__ out)
{
    __shared__ float    cand[SLOTS * NT];        // 8 KB, interleaved per-thread segments
    __shared__ unsigned hist[NB];                // 1 KB
    __shared__ unsigned s_gn, s_flag, s_ovf;
    __shared__ unsigned s_out[3];
    __shared__ float    s_red[NWARP];
    __shared__ float    s_gath[GCAP];
    __shared__ float    s_pos, s_bsum;

    const int tid  = threadIdx.x;
    const int lane = tid & 31;
    const int wid  = tid >> 5;

    #pragma unroll 1
    for (int rep = 0; rep < 2; ++rep) {
        const int row = blockIdx.x + rep * GRIDSZ;
        const float* __restrict__ rowp = in + (size_t)row * NCOLS;
        const int tgt = tg[row];

        __syncthreads();                         // protect smem reuse across rows
        for (int i = tid; i < NB / 4; i += NT)
            ((uint4*)hist)[i] = make_uint4(0, 0, 0, 0);
        if (tid == 0) { s_gn = 0; s_ovf = 0; s_out[0] = SENT; s_pos = rowp[tgt]; }

        // ---- minimal sweep: private-slot compaction only ----
        const float4* __restrict__ p = (const float4*)rowp;
        unsigned mycnt = 0;
        #pragma unroll 8
        for (int it = 0; it < NCOLS / 4 / NT; ++it) {    // 32 iterations
            float4 f = __ldcs(&p[it * NT + tid]);
            if (f.x > THR0) { if (mycnt < SLOTS) cand[mycnt * NT + tid] = f.x; ++mycnt; }
            if (f.y > THR0) { if (mycnt < SLOTS) cand[mycnt * NT + tid] = f.y; ++mycnt; }
            if (f.z > THR0) { if (mycnt < SLOTS) cand[mycnt * NT + tid] = f.z; ++mycnt; }
            if (f.w > THR0) { if (mycnt < SLOTS) cand[mycnt * NT + tid] = f.w; ++mycnt; }
        }
        if (mycnt > SLOTS) s_ovf = 1u;           // plain store, race-free

        // fire-and-forget L2 prefetch of the next row (overlaps select below)
        if (rep == 0) {
            const float* nxt = in + (size_t)(row + GRIDSZ) * NCOLS;
            #pragma unroll
            for (int j = 0; j < 4; ++j)
                prefetch_l2(nxt + (j * NT + tid) * 32);
        }

        const unsigned n_i = mycnt < SLOTS ? mycnt : SLOTS;
        __syncthreads();                         // hist zero + s_pos/s_ovf ordering

        // ---- histogram from own slots (dynamic trip count, ~3 iters) ----
        const float pos = s_pos;
        const unsigned pos_in = (pos > THR0) ? 1u : 0u;
        for (unsigned i = 0; i < n_i; ++i)
            atomicAdd(&hist[binof(cand[i * NT + tid])], 1u);
        if (tid == 0 && pos_in) atomicSub(&hist[binof(pos)], 1u);
        __syncthreads();

        select256_w0(hist, KHARD, s_out);
        __syncthreads();

        bool gmode = (s_out[0] == SENT) || (s_ovf != 0u);
        float sum = 0.0f;
        bool use_key = false;
        unsigned tkey = 0, rmul = 0;
        int bbin = NB;

        if (!gmode) {
            bbin = (int)s_out[0];
            const unsigned rp = KHARD - s_out[1];

            // fused pass over OWN candidates: strict sum + boundary gather
            for (unsigned i = 0; i < n_i; ++i) {
                float x = cand[i * NT + tid];
                int b = binof(x);
                if (b > bbin) sum += softplus(x);
                else if (b == bbin) {
                    unsigned g = atomicAdd(&s_gn, 1u);
                    if (g < GCAP) s_gath[g] = x;
                }
            }
            __syncthreads();

            if (s_gn > GCAP) { gmode = true; sum = 0.0f; }
            else if (tid == 0) {
                int n = (int)s_gn;
                if (pos_in && binof(pos) == bbin) {       // drop one positive instance
                    for (int j = 0; j < n; ++j)
                        if (s_gath[j] == pos) { s_gath[j] = s_gath[n - 1]; --n; break; }
                }
                float bs = 0.0f;                          // top-rp of the boundary bin
                for (int a = 0; a < (int)rp; ++a) {
                    int mi = a; float mv = s_gath[a];
                    for (int b2 = a + 1; b2 < n; ++b2)
                        if (s_gath[b2] > mv) { mv = s_gath[b2]; mi = b2; }
                    s_gath[mi] = s_gath[a]; s_gath[a] = mv;
                    bs += softplus(mv);
                }
                s_bsum = bs;
            }
        }

        if (gmode) {
            // exact 4x8-bit fkey radix select from gmem; never fires for N(0,1)
            use_key = true;
            unsigned prefix = 0, r = KHARD;
            for (int lev = 0; lev < 4; ++lev) {
                const int shift = 24 - 8 * lev;
                for (int i = tid; i < 256; i += NT) hist[i] = 0;
                if (tid == 0) s_out[0] = 0;      // always found below (full row)
                __syncthreads();
                for (int j = tid; j < NCOLS; j += NT) {
                    if (j == tgt) continue;
                    unsigned u = fkey(rowp[j]);
                    bool match = (lev == 0) || (((u ^ prefix) >> (shift + 8)) == 0u);
                    if (match) atomicAdd(&hist[(u >> shift) & 255u], 1u);
                }
                __syncthreads();
                select256_w0(hist, r, s_out);
                __syncthreads();
                prefix |= s_out[0] << shift;
                r -= s_out[1];
                __syncthreads();                 // before next level's zeroing
            }
            tkey = prefix; rmul = r;
            for (int j = tid; j < NCOLS; j += NT) {
                if (j == tgt) continue;
                float x = rowp[j];
                if (fkey(x) > tkey) sum += softplus(x);
            }
        }

        // ---- block reduce strict sum, write row partial ----
        #pragma unroll
        for (int o = 16; o; o >>= 1) sum += __shfl_down_sync(FULLM, sum, o);
        if (lane == 0) s_red[wid] = sum;
        __syncthreads();

        if (tid == 0) {
            float tot = 0.0f;
            #pragma unroll
            for (int w = 0; w < NWARP; ++w) tot += s_red[w];
            if (!use_key) {
                if (pos_in && binof(pos) > bbin) tot -= softplus(pos);
                tot += s_bsum;
            } else {
                tot += (float)rmul * softplus(unfkey(tkey));
            }
            g_partials[row] = DELTA_W * softplus(-pos) + tot / (float)KHARD;
        }
    }

    // ---- once per CTA: completion handshake; last CTA reduces all rows ----
    __syncthreads();
    if (tid == 0) {
        __threadfence();
        unsigned old = atomicAdd(&g_done, 1u);
        s_flag = (old == GRIDSZ - 1) ? 1u : 0u;
    }
    __syncthreads();

    if (s_flag) {
        __threadfence();
        float s = 0.0f;
        for (int i = tid; i < MROWS; i += NT) s += __ldcg(&g_partials[i]);
        #pragma unroll
        for (int o = 16; o; o >>= 1) s += __shfl_down_sync(FULLM, s, o);
        if (lane == 0) s_red[wid] = s;
        __syncthreads();
        if (tid == 0) {
            float tot = 0.0f;
            #pragma unroll
            for (int w = 0; w < NWARP; ++w) tot += s_red[w];
            out[0] = tot / (float)MROWS;
            g_done = 0;                               // reset for next graph replay
        }
    }
}

extern "C" void kernel_launch(void* const* d_in, const int* in_sizes, int n_in,
                              void* d_out, int out_size)
{
    const float* in  = (const float*)d_in[0];
    const int*   tg  = (const int*)d_in[1];
    float*       out = (float*)d_out;
    mmcl_kernel<<<GRIDSZ, NT>>>(in, tg, out);
}

// round 14
// speedup vs baseline: 1.3341x; 1.1896x over previous
#include <cuda_runtime.h>
#include <math.h>
#include <float.h>

#define MROWS   4096
#define NCOLS   16384
#define KHARD   163          // int(0.01 * (16384-1))
#define DELTA_W 5.0f
#define THR0    2.2f
#define NT      128
#define NWARP   (NT / 32)
#define SLOTS   16           // per-thread private candidate slots
#define NB      256          // linear value bins over [THR0, THR0+4)
#define GCAP    64
#define GRIDSZ  2048         // 2 rows per CTA, single wave at 14 CTAs/SM
#define FULLM   0xFFFFFFFFu

__device__ float    g_partials[MROWS];
__device__ unsigned g_done = 0;

__device__ __forceinline__ unsigned fkey(float x) {
    unsigned b = __float_as_uint(x);
    return (b & 0x80000000u) ? ~b : (b | 0x80000000u);
}
__device__ __forceinline__ float unfkey(unsigned k) {
    return (k & 0x80000000u) ? __uint_as_float(k ^ 0x80000000u) : __uint_as_float(~k);
}
__device__ __forceinline__ float softplus(float x) {
    // fast + stable: max(x,0) + log(1 + exp(-|x|)); MUFU-only transcendentals
    return fmaxf(x, 0.0f) + __logf(1.0f + __expf(-fabsf(x)));
}
__device__ __forceinline__ int binof(float x) {          // x > THR0
    int b = (int)((x - THR0) * 64.0f);                   // NB/4 per unit
    return b > NB - 1 ? NB - 1 : b;
}
__device__ __forceinline__ void prefetch_l2(const float* p) {
    asm volatile("prefetch.global.L2 [%0];" :: "l"(p));
}

// Boundary-bin search for the r-th largest over hist[0..B).
// s_out = {bin, count strictly above bin, bin count}. 2 barriers.
__device__ __forceinline__ void select_bin(const unsigned* __restrict__ hist, int B,
                                           unsigned r, unsigned* s_warpS,
                                           unsigned* s_out)
{
    const int tid = threadIdx.x, lane = tid & 31, wid = tid >> 5;
    const int c = (B + NT - 1) / NT;
    unsigned total = 0;
    const int base = tid * c;
    for (int j = 0; j < c; ++j)
        if (base + j < B) total += hist[base + j];
    unsigned incl = total;
    #pragma unroll
    for (int off = 1; off < 32; off <<= 1) {
        unsigned v = __shfl_down_sync(FULLM, incl, off);
        if (lane + off < 32) incl += v;
    }
    if (lane == 0) s_warpS[wid] = incl;
    __syncthreads();
    unsigned hi = 0;
    #pragma unroll
    for (int w = 0; w < NWARP; ++w) if (w > wid) hi += s_warpS[w];
    unsigned S = incl + hi;
    unsigned above_chunk = S - total;
    if (above_chunk < r && S >= r) {
        unsigned run = above_chunk;
        for (int j = c - 1; j >= 0; --j) {
            if (base + j >= B) continue;
            unsigned cnt = hist[base + j];
            if (run + cnt >= r) { s_out[0] = base + j; s_out[1] = run; s_out[2] = cnt; break; }
            run += cnt;
        }
    }
    __syncthreads();
}

extern "C" __global__ void __launch_bounds__(NT, 14)
mmcl_kernel(const float* __restrict__ in, const int* __restrict__ tg,
            float* __restrict__ out)
{
    __shared__ float    cand[SLOTS * NT];       // 8 KB, interleaved per-thread segments
    __shared__ unsigned hist[NB];               // 1 KB
    __shared__ unsigned s_gn, s_flag;
    __shared__ unsigned s_warpS[NWARP];
    __shared__ unsigned s_out[3];
    __shared__ float    s_red[NWARP];
    __shared__ float    s_gath[GCAP];
    __shared__ float    s_pos, s_bsum;

    const int tid  = threadIdx.x;
    const int lane = tid & 31;
    const int wid  = tid >> 5;

    #pragma unroll 1
    for (int rep = 0; rep < 2; ++rep) {
        const int row = blockIdx.x + rep * GRIDSZ;
        const float* __restrict__ rowp = in + (size_t)row * NCOLS;
        const int tgt = tg[row];

        __syncthreads();                         // protect smem reuse across rows
        for (int i = tid; i < NB / 4; i += NT)
            ((uint4*)hist)[i] = make_uint4(0, 0, 0, 0);
        if (tid == 0) { s_gn = 0; s_pos = rowp[tgt]; }

        // ---- minimal sweep: private-slot compaction only ----
        const float4* __restrict__ p = (const float4*)rowp;
        unsigned mycnt = 0;
        #pragma unroll 8
        for (int it = 0; it < NCOLS / 4 / NT; ++it) {    // 32 iterations
            float4 f = __ldcs(&p[it * NT + tid]);
            if (f.x > THR0) { if (mycnt < SLOTS) cand[mycnt * NT + tid] = f.x; ++mycnt; }
            if (f.y > THR0) { if (mycnt < SLOTS) cand[mycnt * NT + tid] = f.y; ++mycnt; }
            if (f.z > THR0) { if (mycnt < SLOTS) cand[mycnt * NT + tid] = f.z; ++mycnt; }
            if (f.w > THR0) { if (mycnt < SLOTS) cand[mycnt * NT + tid] = f.w; ++mycnt; }
        }

        // ---- fire-and-forget L2 prefetch of the NEXT row (overlaps select below) ----
        if (rep == 0) {
            const float* nxt = in + (size_t)(row + GRIDSZ) * NCOLS;
            #pragma unroll
            for (int j = 0; j < 4; ++j)                   // 4 x 128 thr = 512 lines x 128B
                prefetch_l2(nxt + (j * NT + tid) * 32);
        }

        const unsigned wsum = __reduce_add_sync(FULLM, mycnt);
        const unsigned wovf = __ballot_sync(FULLM, mycnt > SLOTS);
        if (lane == 0) s_warpS[wid] = (wsum << 1) | (wovf ? 1u : 0u);
        __syncthreads();
        unsigned nc = 0, ovf = 0;
        #pragma unroll
        for (int w = 0; w < NWARP; ++w) { nc += s_warpS[w] >> 1; ovf |= s_warpS[w] & 1u; }

        const float    pos = s_pos;
        const unsigned pos_in = (pos > THR0) ? 1u : 0u;
        bool gmode = (nc < KHARD + pos_in) || ovf;

        float sum = 0.0f;
        bool use_key = false;
        unsigned tkey = 0, rmul = 0;
        int bbin = NB;

        if (!gmode) {
            // histogram from own slots (few elements each)
            for (unsigned i = 0; i < mycnt; ++i)
                atomicAdd(&hist[binof(cand[i * NT + tid])], 1u);
            if (tid == 0 && pos_in) atomicSub(&hist[binof(pos)], 1u);
            __syncthreads();

            select_bin(hist, NB, KHARD, s_warpS, s_out);
            bbin = (int)s_out[0];
            const unsigned rp = KHARD - s_out[1];

            // fused pass over OWN candidates: strict sum + boundary gather
            for (unsigned i = 0; i < mycnt; ++i) {
                float x = cand[i * NT + tid];
                int b = binof(x);
                if (b > bbin) sum += softplus(x);
                else if (b == bbin) {
                    unsigned g = atomicAdd(&s_gn, 1u);
                    if (g < GCAP) s_gath[g] = x;
                }
            }
            __syncthreads();

            if (s_gn > GCAP) { gmode = true; sum = 0.0f; }
            else if (tid == 0) {
                int n = (int)s_gn;
                if (pos_in && binof(pos) == bbin) {       // drop one positive instance
                    for (int j = 0; j < n; ++j)
                        if (s_gath[j] == pos) { s_gath[j] = s_gath[n - 1]; --n; break; }
                }
                float bs = 0.0f;                          // top-rp of the boundary bin
                for (int a = 0; a < (int)rp; ++a) {
                    int mi = a; float mv = s_gath[a];
                    for (int b2 = a + 1; b2 < n; ++b2)
                        if (s_gath[b2] > mv) { mv = s_gath[b2]; mi = b2; }
                    s_gath[mi] = s_gath[a]; s_gath[a] = mv;
                    bs += softplus(mv);
                }
                s_bsum = bs;
            }
        }

        if (gmode) {
            // exact 4x8-bit fkey radix select from gmem; never fires for N(0,1)
            use_key = true;
            unsigned prefix = 0, r = KHARD;
            for (int lev = 0; lev < 4; ++lev) {
                const int shift = 24 - 8 * lev;
                for (int i = tid; i < 256; i += NT) hist[i] = 0;
                __syncthreads();
                for (int j = tid; j < NCOLS; j += NT) {
                    if (j == tgt) continue;
                    unsigned u = fkey(rowp[j]);
                    bool match = (lev == 0) || (((u ^ prefix) >> (shift + 8)) == 0u);
                    if (match) atomicAdd(&hist[(u >> shift) & 255u], 1u);
                }
                __syncthreads();
                select_bin(hist, 256, r, s_warpS, s_out);
                prefix |= s_out[0] << shift;
                r -= s_out[1];
                __syncthreads();
            }
            tkey = prefix; rmul = r;
            for (int j = tid; j < NCOLS; j += NT) {
                if (j == tgt) continue;
                float x = rowp[j];
                if (fkey(x) > tkey) sum += softplus(x);
            }
        }

        // ---- block reduce strict sum, write row partial ----
        #pragma unroll
        for (int o = 16; o; o >>= 1) sum += __shfl_down_sync(FULLM, sum, o);
        if (lane == 0) s_red[wid] = sum;
        __syncthreads();

        if (tid == 0) {
            float tot = 0.0f;
            #pragma unroll
            for (int w = 0; w < NWARP; ++w) tot += s_red[w];
            if (!use_key) {
                if (pos_in && binof(pos) > bbin) tot -= softplus(pos);
                tot += s_bsum;
            } else {
                tot += (float)rmul * softplus(unfkey(tkey));
            }
            g_partials[row] = DELTA_W * softplus(-pos) + tot / (float)KHARD;
        }
    }

    // ---- once per CTA: completion handshake; last CTA reduces all rows ----
    __syncthreads();
    if (tid == 0) {
        __threadfence();
        unsigned old = atomicAdd(&g_done, 1u);
        s_flag = (old == GRIDSZ - 1) ? 1u : 0u;
    }
    __syncthreads();

    if (s_flag) {
        __threadfence();
        float s = 0.0f;
        for (int i = tid; i < MROWS; i += NT) s += __ldcg(&g_partials[i]);
        #pragma unroll
        for (int o = 16; o; o >>= 1) s += __shfl_down_sync(FULLM, s, o);
        if (lane == 0) s_red[wid] = s;
        __syncthreads();
        if (tid == 0) {
            float tot = 0.0f;
            #pragma unroll
            for (int w = 0; w < NWARP; ++w) tot += s_red[w];
            out[0] = tot / (float)MROWS;
            g_done = 0;                               // reset for next graph replay
        }
    }
}

extern "C" void kernel_launch(void* const* d_in, const int* in_sizes, int n_in,
                              void* d_out, int out_size)
{
    const float* in  = (const float*)d_in[0];
    const int*   tg  = (const int*)d_in[1];
    float*       out = (float*)d_out;
    mmcl_kernel<<<GRIDSZ, NT>>>(in, tg, out);
}